// round 15
// baseline (speedup 1.0000x reference)
#include <cuda_runtime.h>
#include <cuda_bf16.h>
#include <cstdint>

// Fixed problem shape
#define BB 8
#define NN 4096
#define EE 64
#define KK 32

#define DELTA_V 0.5f
#define DELTA_D 1.5f
#define GAMMA   0.001f

#define G1 256            // blocks per kernel
#define TPB 512
#define PTS 128           // points per block
#define SMEM_DYN (PTS * EE * 4)   // 32KB x stash

// Scratch ------------------------------------------------------------------
__device__ float    g_part[G1 * KK * EE];   // per-block centroid partial sums
__device__ float    g_pcnt[G1 * KK];        // per-block cluster counts
__device__ float    g_cent[BB * KK * EE];   // normalized centroids
__device__ int      g_lab[BB * NN];         // labels
__device__ float    g_acc[3];               // L_v, L_d, L_r (unnormalized)
__device__ unsigned g_flag[BB];             // per-batch "centroids ready" flags
__device__ unsigned g_bar = 0;              // finalize counter

__device__ __forceinline__ void cp_async16(void* smem_dst, const void* gmem_src) {
    uint32_t s = (uint32_t)__cvta_generic_to_shared(smem_dst);
    asm volatile("cp.async.cg.shared.global [%0], [%1], 16;" :: "r"(s), "l"(gmem_src));
}
__device__ __forceinline__ void cp_async_wait_all() {
    asm volatile("cp.async.commit_group;\ncp.async.wait_group 0;" ::: "memory");
}

// ===========================================================================
// K1 (R10's best-measured version): cp.async x->smem overlapped with labels;
// counting sort; per-bin register accumulation -> private partial slices.
// ===========================================================================
__global__ void __launch_bounds__(TPB) k_partial(const float* __restrict__ x,
                                                 const float* __restrict__ m) {
    extern __shared__ float sx[];             // [PTS*EE] x stash
    __shared__ int slab[PTS];
    __shared__ int ssorted[PTS];
    __shared__ int sbin[KK], soff[KK], scur[KK];

    int tid = threadIdx.x, lane = tid & 31, warp = tid >> 5;
    int blk = blockIdx.x;
    int pbase = blk * PTS;

    if (tid < KK) sbin[tid] = 0;
    if (blk == 0 && tid < 3) g_acc[tid] = 0.0f;

    // ---- stream entire 32KB x tile via cp.async ---------------------------
    {
        const float4* x4 = (const float4*)(x + (size_t)pbase * EE);
        float4* sx4 = (float4*)sx;
        #pragma unroll
        for (int i = 0; i < 4; ++i)
            cp_async16(&sx4[tid + i * TPB], &x4[tid + i * TPB]);
    }

    // ---- labels from masks while x streams --------------------------------
    #pragma unroll
    for (int it = 0; it < 2; ++it) {
        int p  = it * 64 + warp * 4 + (lane >> 3);
        int k0 = (lane & 7) * 4;
        float4 mv = *(const float4*)(m + (size_t)(pbase + p) * KK + k0);
        float s = mv.x * k0 + mv.y * (k0 + 1) + mv.z * (k0 + 2) + mv.w * (k0 + 3);
        s += __shfl_xor_sync(0xffffffffu, s, 1);
        s += __shfl_xor_sync(0xffffffffu, s, 2);
        s += __shfl_xor_sync(0xffffffffu, s, 4);
        if ((lane & 7) == 0) slab[p] = (int)(s + 0.5f);
    }
    __syncthreads();

    // ---- counting sort -----------------------------------------------------
    if (tid < PTS) atomicAdd(&sbin[slab[tid]], 1);
    __syncthreads();
    if (tid < KK) {
        int c = sbin[tid];
        int pref = c;
        #pragma unroll
        for (int o = 1; o < 32; o <<= 1) {
            int nv = __shfl_up_sync(0xffffffffu, pref, o);
            if (lane >= o) pref += nv;
        }
        soff[tid] = pref - c;
        scur[tid] = pref - c;
    }
    __syncthreads();
    if (tid < PTS) {
        int pos = atomicAdd(&scur[slab[tid]], 1);
        ssorted[pos] = tid;
        g_lab[pbase + tid] = slab[tid];       // persist labels for K3
    }
    cp_async_wait_all();
    __syncthreads();

    // ---- per-bin accumulation from SMEM (no atomics) ----------------------
    #pragma unroll
    for (int kb = 0; kb < 2; ++kb) {
        int k = warp * 2 + kb;
        int start = soff[k], cnt = sbin[k], end = start + cnt;
        float ax = 0.0f, ay = 0.0f;
        for (int base = start; base < end; base += 4) {
            float2 v0 = {0,0}, v1 = {0,0}, v2 = {0,0}, v3 = {0,0};
            v0 = *(const float2*)(sx + ssorted[base] * EE + lane * 2);
            if (base + 1 < end) v1 = *(const float2*)(sx + ssorted[base+1] * EE + lane * 2);
            if (base + 2 < end) v2 = *(const float2*)(sx + ssorted[base+2] * EE + lane * 2);
            if (base + 3 < end) v3 = *(const float2*)(sx + ssorted[base+3] * EE + lane * 2);
            ax += (v0.x + v1.x) + (v2.x + v3.x);
            ay += (v0.y + v1.y) + (v2.y + v3.y);
        }
        float2 acc = {ax, ay};
        *(float2*)(&g_part[(size_t)blk * (KK*EE) + k * EE + lane * 2]) = acc;
        if (lane == 0) g_pcnt[blk * KK + k] = (float)cnt;
    }
}

// ===========================================================================
// K3: in-kernel per-batch reduction (leader block + flag), variance hinge,
//     pairs/reg, finalize. Reduction overlaps other blocks' x prefetch.
// ===========================================================================
__global__ void __launch_bounds__(TPB) k_loss(const float* __restrict__ x,
                                              float* __restrict__ out) {
    extern __shared__ float sx[];             // [PTS*EE] x stash
    __shared__ float sc[KK * EE];             // normalized centroids
    __shared__ float ct[KK * EE];
    __shared__ float sinv[KK];
    __shared__ int   slab[PTS];
    __shared__ float bsum;

    int tid = threadIdx.x, lane = tid & 31;
    int blk = blockIdx.x;
    int pbase = blk * PTS;
    int b = blk >> 5;
    bool leader = ((blk & 31) == 0);

    // ---- x prefetch first: overlaps reduce (leader) or spin (others) ------
    {
        const float4* x4 = (const float4*)(x + (size_t)pbase * EE);
        float4* sx4 = (float4*)sx;
        #pragma unroll
        for (int i = 0; i < 4; ++i)
            cp_async16(&sx4[tid + i * TPB], &x4[tid + i * TPB]);
    }
    if (tid == 0) bsum = 0.0f;
    if (tid < PTS) slab[tid] = g_lab[pbase + tid];

    if (leader) {
        // ---- reduce this batch's 32 partial slices -> sc + g_cent ---------
        if (tid < KK) {
            float c = 0.0f;
            #pragma unroll
            for (int j = 0; j < 32; ++j)
                c += __ldcg(&g_pcnt[((b << 5) | j) * KK + tid]);
            sinv[tid] = 1.0f / c;
        }
        __syncthreads();
        #pragma unroll
        for (int i = 0; i < 4; ++i) {
            int col = tid + i * TPB;          // 4 of 2048 columns per thread
            float s0 = 0.0f, s1 = 0.0f, s2 = 0.0f, s3 = 0.0f;
            #pragma unroll
            for (int j = 0; j < 32; j += 4) {
                s0 += __ldcg(&g_part[(size_t)((b << 5) | (j    )) * (KK*EE) + col]);
                s1 += __ldcg(&g_part[(size_t)((b << 5) | (j + 1)) * (KK*EE) + col]);
                s2 += __ldcg(&g_part[(size_t)((b << 5) | (j + 2)) * (KK*EE) + col]);
                s3 += __ldcg(&g_part[(size_t)((b << 5) | (j + 3)) * (KK*EE) + col]);
            }
            float v = ((s0 + s1) + (s2 + s3)) * sinv[col >> 6];
            sc[col] = v;
            g_cent[b * (KK*EE) + col] = v;
        }
        __threadfence();
        __syncthreads();
        if (tid == 0) atomicExch(&g_flag[b], 1u);   // release
    } else {
        if (tid == 0) {
            while (*(volatile unsigned*)&g_flag[b] == 0u) __nanosleep(64);
        }
        __syncthreads();
        __threadfence();                      // acquire ordering for g_cent reads
        ((float4*)sc)[tid] = __ldcg(((const float4*)(g_cent + b * (KK*EE))) + tid);
    }
    cp_async_wait_all();
    __syncthreads();

    // ---- variance hinge: 16-lane group per point, 2-pt ILP, from SMEM -----
    {
        int gid = tid >> 4, gl = tid & 15;
        float lv = 0.0f;
        #pragma unroll
        for (int it = 0; it < 2; ++it) {
            int iA = it * 64 + gid;
            int iB = iA + 32;
            int labA = slab[iA], labB = slab[iB];
            float4 xA = ((const float4*)sx)[iA * 16 + gl];
            float4 xB = ((const float4*)sx)[iB * 16 + gl];
            float4 cA = ((const float4*)sc)[labA * 16 + gl];
            float4 cB = ((const float4*)sc)[labB * 16 + gl];
            float a0 = xA.x - cA.x, a1 = xA.y - cA.y, a2 = xA.z - cA.z, a3 = xA.w - cA.w;
            float b0 = xB.x - cB.x, b1 = xB.y - cB.y, b2 = xB.z - cB.z, b3 = xB.w - cB.w;
            float sqA = a0 * a0 + a1 * a1 + a2 * a2 + a3 * a3;
            float sqB = b0 * b0 + b1 * b1 + b2 * b2 + b3 * b3;
            #pragma unroll
            for (int o = 8; o; o >>= 1) {
                sqA += __shfl_xor_sync(0xffffffffu, sqA, o);
                sqB += __shfl_xor_sync(0xffffffffu, sqB, o);
            }
            if (gl == 0) {
                float hA = sqrtf(sqA) - DELTA_V;
                float hB = sqrtf(sqB) - DELTA_V;
                if (hA > 0.0f) lv += hA * hA;
                if (hB > 0.0f) lv += hB * hB;
            }
        }
        if (gl == 0) atomicAdd(&bsum, lv);
        __syncthreads();
        if (tid == 0) atomicAdd(&g_acc[0], bsum);
    }

    // ---- pairwise hinge + reg term (leader blocks only) -------------------
    if (leader) {
        for (int i = tid; i < KK * EE; i += TPB) {
            int e = i >> 5, k = i & 31;
            ct[i] = sc[k * EE + e];            // transposed, lane-contiguous
        }
        __syncthreads();

        float ld = 0.0f, lr = 0.0f;
        #pragma unroll
        for (int rep = 0; rep < 2; ++rep) {
            int pr = rep * TPB + tid;
            int k1 = pr >> 5, k2 = pr & 31;
            float sq = 0.0f;
            if (k1 == k2) {
                #pragma unroll
                for (int e = 0; e < EE; e++) { float v = sc[k1 * EE + e]; sq += v * v; }
                lr += sqrtf(sq);
            } else {
                #pragma unroll
                for (int e = 0; e < EE; e++) {
                    float d = sc[k1 * EE + e] - ct[e * KK + k2];
                    sq += d * d;
                }
                float h = 2.0f * DELTA_D - sqrtf(sq);
                if (h > 0.0f) ld += h * h;
            }
        }
        #pragma unroll
        for (int o = 16; o; o >>= 1) {
            ld += __shfl_xor_sync(0xffffffffu, ld, o);
            lr += __shfl_xor_sync(0xffffffffu, lr, o);
        }
        if (lane == 0) {
            atomicAdd(&g_acc[1], ld);
            atomicAdd(&g_acc[2], lr);
        }
    }

    // ---- finalize: last arrival writes output + resets flags --------------
    __syncthreads();
    if (tid == 0) {
        __threadfence();
        unsigned r = atomicAdd(&g_bar, 1u);
        if (r == G1 - 1) {                     // all blocks passed their spins
            float Lv = *(volatile float*)&g_acc[0] / (float)(BB * NN);
            float Ld = *(volatile float*)&g_acc[1] / (float)(BB * KK * (KK - 1));
            float Lr = *(volatile float*)&g_acc[2] / (float)(BB * KK);
            out[0] = Lv + Ld + GAMMA * Lr;
            #pragma unroll
            for (int j = 0; j < BB; ++j) g_flag[j] = 0u;
            __threadfence();
            atomicExch(&g_bar, 0u);            // ready for next replay
        }
    }
}

// --------------------------------------------------------------------------
extern "C" void kernel_launch(void* const* d_in, const int* in_sizes, int n_in,
                              void* d_out, int out_size) {
    const float* x = (const float*)d_in[0];
    const float* m = (const float*)d_in[1];
    if (in_sizes[0] == BB * NN * KK && in_sizes[1] == BB * NN * EE) {
        x = (const float*)d_in[1];
        m = (const float*)d_in[0];
    }
    cudaFuncSetAttribute(k_partial, cudaFuncAttributeMaxDynamicSharedMemorySize, SMEM_DYN);
    cudaFuncSetAttribute(k_loss,    cudaFuncAttributeMaxDynamicSharedMemorySize, SMEM_DYN);
    k_partial<<<G1, TPB, SMEM_DYN>>>(x, m);
    k_loss<<<G1, TPB, SMEM_DYN>>>(x, (float*)d_out);
}

// round 16
// speedup vs baseline: 1.2714x; 1.2714x over previous
#include <cuda_runtime.h>
#include <cuda_bf16.h>
#include <cooperative_groups.h>
#include <cstdint>

namespace cg = cooperative_groups;

// Fixed problem shape
#define BB 8
#define NN 4096
#define EE 64
#define KK 32

#define DELTA_V 0.5f
#define DELTA_D 1.5f
#define GAMMA   0.001f

#define CLUSTER 8
#define TPB  512
#define CPTS 512                       // points per CTA
#define GRID (BB * NN / CPTS)          // 64 CTAs = 8 clusters of 8
#define SMEM_DYN (CPTS * EE * 4)       // 128KB x stash

// Globals (zero-initialized at load; finalizer resets after each run) -------
__device__ float    g_acc[3];          // L_v, L_d, L_r (unnormalized)
__device__ unsigned g_bar;             // finalize counter

__device__ __forceinline__ void cp_async16(void* smem_dst, const void* gmem_src) {
    uint32_t s = (uint32_t)__cvta_generic_to_shared(smem_dst);
    asm volatile("cp.async.cg.shared.global [%0], [%1], 16;" :: "r"(s), "l"(gmem_src));
}
__device__ __forceinline__ void cp_async_wait_all() {
    asm volatile("cp.async.commit_group;\ncp.async.wait_group 0;" ::: "memory");
}

// ===========================================================================
// One kernel: per-CTA sort+partials, cluster DSMEM centroid all-reduce,
// var hinge from SMEM-resident x, pairs on rank 0, global finalize.
// ===========================================================================
__global__ void __launch_bounds__(TPB) __cluster_dims__(CLUSTER, 1, 1)
fused(const float* __restrict__ x, const float* __restrict__ m,
      float* __restrict__ out) {
    extern __shared__ float sx[];      // [CPTS*EE] x tile (persists whole kernel)
    __shared__ float ps[KK * EE];      // partial centroid sums (this CTA)
    __shared__ float pc[KK];           // partial counts
    __shared__ float red[KK * EE / CLUSTER];  // reduced+normalized slice (256)
    __shared__ float scinv[KK / CLUSTER];     // slice count reciprocals (4)
    __shared__ float sc[KK * EE];      // full normalized centroids
    __shared__ float ct[KK * EE];      // transposed (rank 0, pairs)
    __shared__ int   slab[CPTS];
    __shared__ int   ssorted[CPTS];
    __shared__ int   sbin[KK], soff[KK], scur[KK];
    __shared__ float bsum;

    cg::cluster_group cluster = cg::this_cluster();
    int rank = cluster.block_rank();

    int tid = threadIdx.x, lane = tid & 31, warp = tid >> 5;
    int pbase = blockIdx.x * CPTS;

    if (tid < KK) sbin[tid] = 0;
    if (tid == 0) bsum = 0.0f;

    // ---- stream 128KB x tile via cp.async ---------------------------------
    {
        const float4* x4 = (const float4*)(x + (size_t)pbase * EE);
        float4* sx4 = (float4*)sx;
        #pragma unroll
        for (int i = 0; i < 16; ++i)
            cp_async16(&sx4[tid + i * TPB], &x4[tid + i * TPB]);
    }

    // ---- labels from masks (perfectly coalesced, 8 lanes per point) -------
    #pragma unroll
    for (int it = 0; it < 8; ++it) {
        int p  = it * 64 + warp * 4 + (lane >> 3);
        int k0 = (lane & 7) * 4;
        float4 mv = *(const float4*)(m + (size_t)(pbase + p) * KK + k0);
        float s = mv.x * k0 + mv.y * (k0 + 1) + mv.z * (k0 + 2) + mv.w * (k0 + 3);
        s += __shfl_xor_sync(0xffffffffu, s, 1);
        s += __shfl_xor_sync(0xffffffffu, s, 2);
        s += __shfl_xor_sync(0xffffffffu, s, 4);
        if ((lane & 7) == 0) slab[p] = (int)(s + 0.5f);
    }
    __syncthreads();

    // ---- counting sort of 512 points --------------------------------------
    if (tid < CPTS) atomicAdd(&sbin[slab[tid]], 1);
    __syncthreads();
    if (tid < KK) {
        int c = sbin[tid];
        int pref = c;
        #pragma unroll
        for (int o = 1; o < 32; o <<= 1) {
            int nv = __shfl_up_sync(0xffffffffu, pref, o);
            if (lane >= o) pref += nv;
        }
        soff[tid] = pref - c;
        scur[tid] = pref - c;
    }
    __syncthreads();
    if (tid < CPTS) {
        int pos = atomicAdd(&scur[slab[tid]], 1);
        ssorted[pos] = tid;
    }
    cp_async_wait_all();
    __syncthreads();

    // ---- per-bin accumulation from SMEM (warp owns 2 bins) ----------------
    #pragma unroll
    for (int kb = 0; kb < 2; ++kb) {
        int k = warp * 2 + kb;
        int start = soff[k], cnt = sbin[k], end = start + cnt;
        float ax = 0.0f, ay = 0.0f;
        for (int base = start; base < end; base += 4) {
            float2 v0 = {0,0}, v1 = {0,0}, v2 = {0,0}, v3 = {0,0};
            v0 = *(const float2*)(sx + ssorted[base] * EE + lane * 2);
            if (base + 1 < end) v1 = *(const float2*)(sx + ssorted[base+1] * EE + lane * 2);
            if (base + 2 < end) v2 = *(const float2*)(sx + ssorted[base+2] * EE + lane * 2);
            if (base + 3 < end) v3 = *(const float2*)(sx + ssorted[base+3] * EE + lane * 2);
            ax += (v0.x + v1.x) + (v2.x + v3.x);
            ay += (v0.y + v1.y) + (v2.y + v3.y);
        }
        ps[k * EE + lane * 2]     = ax;
        ps[k * EE + lane * 2 + 1] = ay;
        if (lane == 0) pc[k] = (float)cnt;
    }

    cluster.sync();                    // all CTAs' partials visible in DSMEM

    // ---- rank reduces its 256-column slice across 8 peers -----------------
    if (tid < KK / CLUSTER) {          // counts for slice clusters
        int kk = rank * (KK / CLUSTER) + tid;
        float c = 0.0f;
        #pragma unroll
        for (int peer = 0; peer < CLUSTER; ++peer)
            c += cluster.map_shared_rank(pc, peer)[kk];
        scinv[tid] = 1.0f / c;
    }
    __syncthreads();
    if (tid < KK * EE / CLUSTER) {     // 256 threads, one column each
        int col = rank * (KK * EE / CLUSTER) + tid;
        float s = 0.0f;
        #pragma unroll
        for (int peer = 0; peer < CLUSTER; ++peer)
            s += cluster.map_shared_rank(ps, peer)[col];
        red[tid] = s * scinv[tid >> 6];
    }

    cluster.sync();                    // all reduced slices ready

    // ---- gather full normalized centroid set from peers -------------------
    #pragma unroll
    for (int i = 0; i < 4; ++i) {
        int idx = tid + i * TPB;       // 0..2047
        int owner = idx >> 8;
        sc[idx] = cluster.map_shared_rank(red, owner)[idx & 255];
    }

    cluster.sync();                    // safe: no CTA exits while peers read

    __syncthreads();

    // ---- variance hinge: 16-lane group per point, 2-pt ILP, all SMEM ------
    {
        int gid = tid >> 4, gl = tid & 15;
        float lv = 0.0f;
        #pragma unroll
        for (int it = 0; it < 8; ++it) {
            int iA = it * 64 + gid;
            int iB = iA + 32;
            int labA = slab[iA], labB = slab[iB];
            float4 xA = ((const float4*)sx)[iA * 16 + gl];
            float4 xB = ((const float4*)sx)[iB * 16 + gl];
            float4 cA = ((const float4*)sc)[labA * 16 + gl];
            float4 cB = ((const float4*)sc)[labB * 16 + gl];
            float a0 = xA.x - cA.x, a1 = xA.y - cA.y, a2 = xA.z - cA.z, a3 = xA.w - cA.w;
            float b0 = xB.x - cB.x, b1 = xB.y - cB.y, b2 = xB.z - cB.z, b3 = xB.w - cB.w;
            float sqA = a0 * a0 + a1 * a1 + a2 * a2 + a3 * a3;
            float sqB = b0 * b0 + b1 * b1 + b2 * b2 + b3 * b3;
            #pragma unroll
            for (int o = 8; o; o >>= 1) {
                sqA += __shfl_xor_sync(0xffffffffu, sqA, o);
                sqB += __shfl_xor_sync(0xffffffffu, sqB, o);
            }
            if (gl == 0) {
                float hA = sqrtf(sqA) - DELTA_V;
                float hB = sqrtf(sqB) - DELTA_V;
                if (hA > 0.0f) lv += hA * hA;
                if (hB > 0.0f) lv += hB * hB;
            }
        }
        if (gl == 0) atomicAdd(&bsum, lv);
        __syncthreads();
        if (tid == 0) atomicAdd(&g_acc[0], bsum);
    }

    // ---- pairwise hinge + reg term (cluster rank 0 only) ------------------
    if (rank == 0) {
        for (int i = tid; i < KK * EE; i += TPB) {
            int e = i >> 5, k = i & 31;
            ct[i] = sc[k * EE + e];        // transposed, lane-contiguous
        }
        __syncthreads();

        float ld = 0.0f, lr = 0.0f;
        #pragma unroll
        for (int rep = 0; rep < 2; ++rep) {
            int pr = rep * TPB + tid;
            int k1 = pr >> 5, k2 = pr & 31;
            float sq = 0.0f;
            if (k1 == k2) {
                #pragma unroll
                for (int e = 0; e < EE; e++) { float v = sc[k1 * EE + e]; sq += v * v; }
                lr += sqrtf(sq);
            } else {
                #pragma unroll
                for (int e = 0; e < EE; e++) {
                    float d = sc[k1 * EE + e] - ct[e * KK + k2];
                    sq += d * d;
                }
                float h = 2.0f * DELTA_D - sqrtf(sq);
                if (h > 0.0f) ld += h * h;
            }
        }
        #pragma unroll
        for (int o = 16; o; o >>= 1) {
            ld += __shfl_xor_sync(0xffffffffu, ld, o);
            lr += __shfl_xor_sync(0xffffffffu, lr, o);
        }
        if (lane == 0) {
            atomicAdd(&g_acc[1], ld);
            atomicAdd(&g_acc[2], lr);
        }
    }

    // ---- finalize: last arrival writes output, resets accumulators --------
    __syncthreads();
    if (tid == 0) {
        __threadfence();
        unsigned r = atomicAdd(&g_bar, 1u);
        if (r == GRID - 1) {               // all adds fenced before arrivals
            float Lv = *(volatile float*)&g_acc[0] / (float)(BB * NN);
            float Ld = *(volatile float*)&g_acc[1] / (float)(BB * KK * (KK - 1));
            float Lr = *(volatile float*)&g_acc[2] / (float)(BB * KK);
            out[0] = Lv + Ld + GAMMA * Lr;
            g_acc[0] = 0.0f; g_acc[1] = 0.0f; g_acc[2] = 0.0f;
            __threadfence();
            atomicExch(&g_bar, 0u);        // ready for next graph replay
        }
    }
}

// --------------------------------------------------------------------------
extern "C" void kernel_launch(void* const* d_in, const int* in_sizes, int n_in,
                              void* d_out, int out_size) {
    const float* x = (const float*)d_in[0];
    const float* m = (const float*)d_in[1];
    if (in_sizes[0] == BB * NN * KK && in_sizes[1] == BB * NN * EE) {
        x = (const float*)d_in[1];
        m = (const float*)d_in[0];
    }
    cudaFuncSetAttribute(fused, cudaFuncAttributeMaxDynamicSharedMemorySize, SMEM_DYN);
    fused<<<GRID, TPB, SMEM_DYN>>>(x, m, (float*)d_out);
}